// round 2
// baseline (speedup 1.0000x reference)
#include <cuda_runtime.h>
#include <cuda_bf16.h>
#include <math.h>

#define BB 4
#define NN 8192
#define SS 2048
#define CF 64
#define OUTCH 384

// ---------------- scratch (__device__ globals; no allocation) ----------------
__device__ float g_featsT[(long)BB * NN * CF];     // [b][n][c]
__device__ float g_xyzT[(long)BB * 3 * NN];        // [b][d][n]
__device__ float g_pn2[(long)BB * NN];             // |p|^2
__device__ float g_newxyz[(long)BB * SS * 3];      // centers
__device__ float g_q2[(long)BB * SS];              // |q|^2
__device__ int   g_ballidx[(long)BB * SS * 112];   // 16+32+64 per query
__device__ float g_bufA[(long)96 * BB * SS * 64];  // 96  x 524288
__device__ float g_bufB[(long)128 * BB * SS * 64]; // 128 x 524288
__device__ double g_stats[256];                    // [sum(0..127), sumsq(128..255)]
__device__ float g_a[128];
__device__ float g_beta[128];

// ---------------- prep: transpose features, xyz SoA + |p|^2 ----------------
__global__ void transpose_feats_kernel(const float* __restrict__ f) {
    __shared__ float tile[32][33];
    int b = blockIdx.z;
    int n0 = blockIdx.x * 32, c0 = blockIdx.y * 32;
    int x = threadIdx.x, y = threadIdx.y;
    for (int r = y; r < 32; r += 8)
        tile[r][x] = f[((long)b * CF + c0 + r) * NN + n0 + x];
    __syncthreads();
    for (int r = y; r < 32; r += 8)
        g_featsT[((long)b * NN + n0 + r) * CF + c0 + x] = tile[x][r];
}

__global__ void prep_xyz_kernel(const float* __restrict__ xyz) {
    int i = blockIdx.x * blockDim.x + threadIdx.x;
    if (i >= BB * NN) return;
    int b = i / NN, n = i % NN;
    float x = xyz[(long)i * 3 + 0];
    float y = xyz[(long)i * 3 + 1];
    float z = xyz[(long)i * 3 + 2];
    g_xyzT[((long)b * 3 + 0) * NN + n] = x;
    g_xyzT[((long)b * 3 + 1) * NN + n] = y;
    g_xyzT[((long)b * 3 + 2) * NN + n] = z;
    g_pn2[i] = __fadd_rn(__fadd_rn(__fmul_rn(x, x), __fmul_rn(y, y)), __fmul_rn(z, z));
}

// ---------------- FPS: one block per batch ----------------
__global__ void fps_kernel(const float* __restrict__ xyz, float* __restrict__ out_newxyz) {
    extern __shared__ float sm[];
    float* sx = sm;
    float* sy = sm + NN;
    float* sz = sm + 2 * NN;
    __shared__ float swv[32];
    __shared__ int   swi[32];
    __shared__ int   sfar;

    int b = blockIdx.x;
    int tid = threadIdx.x;
    int lane = tid & 31, wid = tid >> 5;

    for (int i = tid; i < NN; i += 1024) {
        sx[i] = xyz[((long)b * NN + i) * 3 + 0];
        sy[i] = xyz[((long)b * NN + i) * 3 + 1];
        sz[i] = xyz[((long)b * NN + i) * 3 + 2];
    }
    float dcur[8];
#pragma unroll
    for (int j = 0; j < 8; ++j) dcur[j] = 3.4e38f;
    int far = 0;
    __syncthreads();

    for (int it = 0; it < SS; ++it) {
        float fx = sx[far], fy = sy[far], fz = sz[far];
        if (tid == 0) {
            long q = (long)b * SS + it;
            out_newxyz[q * 3 + 0] = fx;
            out_newxyz[q * 3 + 1] = fy;
            out_newxyz[q * 3 + 2] = fz;
            g_newxyz[q * 3 + 0] = fx;
            g_newxyz[q * 3 + 1] = fy;
            g_newxyz[q * 3 + 2] = fz;
            g_q2[q] = __fadd_rn(__fadd_rn(__fmul_rn(fx, fx), __fmul_rn(fy, fy)), __fmul_rn(fz, fz));
        }
        float mv = -1.0f;
        int mi = 0;
#pragma unroll
        for (int j = 0; j < 8; ++j) {
            int i = tid + j * 1024;
            float dx = __fadd_rn(sx[i], -fx);
            float dy = __fadd_rn(sy[i], -fy);
            float dz = __fadd_rn(sz[i], -fz);
            float d = __fadd_rn(__fadd_rn(__fmul_rn(dx, dx), __fmul_rn(dy, dy)), __fmul_rn(dz, dz));
            float dn = fminf(dcur[j], d);
            dcur[j] = dn;
            if (dn > mv) { mv = dn; mi = i; }
        }
#pragma unroll
        for (int off = 16; off > 0; off >>= 1) {
            float ov = __shfl_down_sync(0xffffffffu, mv, off);
            int   oi = __shfl_down_sync(0xffffffffu, mi, off);
            if (ov > mv || (ov == mv && oi < mi)) { mv = ov; mi = oi; }
        }
        if (lane == 0) { swv[wid] = mv; swi[wid] = mi; }
        __syncthreads();
        if (wid == 0) {
            float v = swv[lane];
            int   ii = swi[lane];
#pragma unroll
            for (int off = 16; off > 0; off >>= 1) {
                float ov = __shfl_down_sync(0xffffffffu, v, off);
                int   oi = __shfl_down_sync(0xffffffffu, ii, off);
                if (ov > v || (ov == v && oi < ii)) { v = ov; ii = oi; }
            }
            if (lane == 0) sfar = ii;
        }
        __syncthreads();
        far = sfar;
    }
}

// ---------------- ball query: 1 warp per (b, s), all 3 radii ----------------
__global__ void ballq_kernel() {
    int warp = (blockIdx.x * blockDim.x + threadIdx.x) >> 5;
    int lane = threadIdx.x & 31;
    if (warp >= BB * SS) return;
    int b = warp / SS;
    float qx = g_newxyz[(long)warp * 3 + 0];
    float qy = g_newxyz[(long)warp * 3 + 1];
    float qz = g_newxyz[(long)warp * 3 + 2];
    float q2 = g_q2[warp];
    const float rr0 = 0.1f * 0.1f, rr1 = 0.2f * 0.2f, rr2 = 0.4f * 0.4f;
    int c0 = 0, c1 = 0, c2 = 0;
    int f0 = NN - 1, f1 = NN - 1, f2 = NN - 1;
    int* ball = g_ballidx + (long)warp * 112;
    unsigned lanemask = (1u << lane) - 1u;

    const float* px0 = &g_xyzT[((long)b * 3 + 0) * NN];
    const float* py0 = &g_xyzT[((long)b * 3 + 1) * NN];
    const float* pz0 = &g_xyzT[((long)b * 3 + 2) * NN];
    const float* pn2a = &g_pn2[(long)b * NN];

    for (int n0 = 0; n0 < NN; n0 += 32) {
        int n = n0 + lane;
        float px = px0[n], py = py0[n], pz = pz0[n];
        float pn2 = pn2a[n];
        float dot = __fadd_rn(__fadd_rn(__fmul_rn(qx, px), __fmul_rn(qy, py)), __fmul_rn(qz, pz));
        float d2 = __fadd_rn(__fadd_rn(q2, pn2), -__fmul_rn(2.0f, dot));
        bool in0 = d2 < rr0, in1 = d2 < rr1, in2 = d2 < rr2;
        unsigned m0 = __ballot_sync(0xffffffffu, in0);
        unsigned m1 = __ballot_sync(0xffffffffu, in1);
        unsigned m2 = __ballot_sync(0xffffffffu, in2);
        if (c0 < 16) {
            if (c0 == 0 && m0) f0 = n0 + __ffs(m0) - 1;
            int pos = c0 + __popc(m0 & lanemask);
            if (in0 && pos < 16) ball[pos] = n;
            c0 = min(16, c0 + __popc(m0));
        }
        if (c1 < 32) {
            if (c1 == 0 && m1) f1 = n0 + __ffs(m1) - 1;
            int pos = c1 + __popc(m1 & lanemask);
            if (in1 && pos < 32) ball[16 + pos] = n;
            c1 = min(32, c1 + __popc(m1));
        }
        if (c2 < 64) {
            if (c2 == 0 && m2) f2 = n0 + __ffs(m2) - 1;
            int pos = c2 + __popc(m2 & lanemask);
            if (in2 && pos < 64) ball[48 + pos] = n;
            c2 = min(64, c2 + __popc(m2));
        }
        if (c0 >= 16 && c1 >= 32 && c2 >= 64) break;
    }
    for (int p = c0 + lane; p < 16; p += 32) ball[p] = f0;
    for (int p = c1 + lane; p < 32; p += 32) ball[16 + p] = f1;
    for (int p = c2 + lane; p < 64; p += 32) ball[48 + p] = f2;
}

// ---------------- gather: build x0 [67][P] ----------------
__global__ void gather_kernel(int K, int off, float* __restrict__ X, int P) {
    int p = blockIdx.x * 256 + threadIdx.x;
    if (p >= P) return;
    int q = p / K, k = p - q * K;
    int b = q / SS;
    int idx = g_ballidx[(long)q * 112 + off + k];
#pragma unroll
    for (int c = 0; c < 3; ++c)
        X[(long)c * P + p] = g_xyzT[((long)b * 3 + c) * NN + idx] - g_newxyz[(long)q * 3 + c];
    const float* fr = &g_featsT[((long)b * NN + idx) * CF];
#pragma unroll 8
    for (int c = 0; c < CF; ++c)
        X[(long)(3 + c) * P + p] = fr[c];
}

// ---------------- GEMM with optional BN+ReLU fold on input, stats in epilogue ----------------
__global__ void __launch_bounds__(256) gemm_kernel(
    const float* __restrict__ Wg, int O, int C,
    const float* __restrict__ X, float* __restrict__ Y, int P, int fold) {
    __shared__ __align__(16) float Wc[8][128];
    __shared__ __align__(16) float Xs[8][128];
    int tid = threadIdx.x;
    int opg = tid >> 4, ppg = tid & 15;
    int p0 = blockIdx.x * 128;

    float acc[8][8];
#pragma unroll
    for (int i = 0; i < 8; ++i)
#pragma unroll
        for (int j = 0; j < 8; ++j) acc[i][j] = 0.0f;

    for (int cc0 = 0; cc0 < C; cc0 += 8) {
#pragma unroll
        for (int l = tid; l < 1024; l += 256) {
            int o = l >> 3, cc = l & 7;
            int c = cc0 + cc;
            Wc[cc][o] = (o < O && c < C) ? Wg[(long)o * C + c] : 0.0f;
        }
#pragma unroll
        for (int l = tid; l < 1024; l += 256) {
            int cc = l >> 7, pp = l & 127;
            int c = cc0 + cc;
            float v = 0.0f;
            if (c < C) {
                v = X[(long)c * P + p0 + pp];
                if (fold) v = fmaxf(0.0f, fmaf(g_a[c], v, g_beta[c]));
            }
            Xs[cc][pp] = v;
        }
        __syncthreads();
#pragma unroll
        for (int cc = 0; cc < 8; ++cc) {
            float4 x0v = *(const float4*)&Xs[cc][ppg * 8];
            float4 x1v = *(const float4*)&Xs[cc][ppg * 8 + 4];
            float4 w0v = *(const float4*)&Wc[cc][opg * 8];
            float4 w1v = *(const float4*)&Wc[cc][opg * 8 + 4];
            float xv[8] = {x0v.x, x0v.y, x0v.z, x0v.w, x1v.x, x1v.y, x1v.z, x1v.w};
            float wv[8] = {w0v.x, w0v.y, w0v.z, w0v.w, w1v.x, w1v.y, w1v.z, w1v.w};
#pragma unroll
            for (int i = 0; i < 8; ++i)
#pragma unroll
                for (int j = 0; j < 8; ++j)
                    acc[i][j] = fmaf(wv[i], xv[j], acc[i][j]);
        }
        __syncthreads();
    }

    // epilogue: store + per-channel stats
#pragma unroll
    for (int i = 0; i < 8; ++i) {
        int o = opg * 8 + i;
        float s = 0.0f, sq = 0.0f;
#pragma unroll
        for (int j = 0; j < 8; ++j) {
            float v = acc[i][j];
            s += v;
            sq = fmaf(v, v, sq);
        }
        if (o < O) {
            float4 v0 = make_float4(acc[i][0], acc[i][1], acc[i][2], acc[i][3]);
            float4 v1 = make_float4(acc[i][4], acc[i][5], acc[i][6], acc[i][7]);
            *(float4*)&Y[(long)o * P + p0 + ppg * 8] = v0;
            *(float4*)&Y[(long)o * P + p0 + ppg * 8 + 4] = v1;
        }
        // reduce across the 16 threads sharing this o (contiguous half-warp)
#pragma unroll
        for (int off = 8; off > 0; off >>= 1) {
            s  += __shfl_down_sync(0xffffffffu, s, off, 16);
            sq += __shfl_down_sync(0xffffffffu, sq, off, 16);
        }
        if (ppg == 0 && o < O) {
            atomicAdd(&g_stats[o], (double)s);
            atomicAdd(&g_stats[128 + o], (double)sq);
        }
    }
}

// ---------------- finalize BN params ----------------
__global__ void finalize_kernel(int O, int P, const float* __restrict__ g, const float* __restrict__ b) {
    int o = threadIdx.x;
    if (o >= O) return;
    double m = g_stats[o] / (double)P;
    double var = g_stats[128 + o] / (double)P - m * m;
    float aa = g[o] / sqrtf((float)var + 1e-5f);
    g_a[o] = aa;
    g_beta[o] = fmaf(-(float)m, aa, b[o]);
}

// ---------------- maxpool over K with BN+ReLU fold ----------------
__global__ void maxpool_kernel(const float* __restrict__ Y, int K, int coff,
                               float* __restrict__ out, int P) {
    int gw = (blockIdx.x * blockDim.x + threadIdx.x) >> 5;
    int lane = threadIdx.x & 31;
    if (gw >= BB * SS * 128) return;
    int q = gw % (BB * SS);
    int o = gw / (BB * SS);
    int b = q / SS, s = q % SS;
    float a = g_a[o], be = g_beta[o];
    const float* yp = &Y[(long)o * P + (long)q * K];
    float m = 0.0f;
    for (int k = lane; k < K; k += 32)
        m = fmaxf(m, fmaxf(0.0f, fmaf(a, yp[k], be)));
#pragma unroll
    for (int off = 16; off > 0; off >>= 1)
        m = fmaxf(m, __shfl_down_sync(0xffffffffu, m, off));
    if (lane == 0)
        out[((long)b * OUTCH + coff + o) * SS + s] = m;
}

// ---------------- launch ----------------
extern "C" void kernel_launch(void* const* d_in, const int* in_sizes, int n_in,
                              void* d_out, int out_size) {
    (void)in_sizes; (void)n_in; (void)out_size;
    const float* xyz   = (const float*)d_in[0];
    const float* feats = (const float*)d_in[1];
    const float* w1 = (const float*)d_in[2];
    const float* g1 = (const float*)d_in[3];
    const float* b1 = (const float*)d_in[4];
    const float* w2 = (const float*)d_in[5];
    const float* g2 = (const float*)d_in[6];
    const float* b2 = (const float*)d_in[7];
    const float* w3 = (const float*)d_in[8];
    const float* g3 = (const float*)d_in[9];
    const float* b3 = (const float*)d_in[10];
    float* out = (float*)d_out;
    float* outF = out + (long)BB * SS * 3;

    float *bufA = nullptr, *bufB = nullptr;
    double* stats = nullptr;
    cudaGetSymbolAddress((void**)&bufA, g_bufA);
    cudaGetSymbolAddress((void**)&bufB, g_bufB);
    cudaGetSymbolAddress((void**)&stats, g_stats);

    cudaFuncSetAttribute(fps_kernel, cudaFuncAttributeMaxDynamicSharedMemorySize, 3 * NN * 4);

    dim3 tb(32, 8), tg(NN / 32, CF / 32, BB);
    transpose_feats_kernel<<<tg, tb>>>(feats);
    prep_xyz_kernel<<<(BB * NN) / 256, 256>>>(xyz);
    fps_kernel<<<BB, 1024, 3 * NN * 4>>>(xyz, out);
    ballq_kernel<<<(BB * SS * 32) / 256, 256>>>();

    const int Ks[3] = {16, 32, 64};
    const int offs[3] = {0, 16, 48};
    const int coffs[3] = {0, 128, 256};
    for (int i = 0; i < 3; ++i) {
        int K = Ks[i];
        int P = BB * SS * K;
        gather_kernel<<<P / 256, 256>>>(K, offs[i], bufA, P);

        cudaMemsetAsync(stats, 0, 256 * sizeof(double));
        gemm_kernel<<<P / 128, 256>>>(w1 + (long)i * 64 * 67, 64, 67, bufA, bufB, P, 0);
        finalize_kernel<<<1, 128>>>(64, P, g1 + i * 64, b1 + i * 64);

        cudaMemsetAsync(stats, 0, 256 * sizeof(double));
        gemm_kernel<<<P / 128, 256>>>(w2 + (long)i * 96 * 64, 96, 64, bufB, bufA, P, 1);
        finalize_kernel<<<1, 128>>>(96, P, g2 + i * 96, b2 + i * 96);

        cudaMemsetAsync(stats, 0, 256 * sizeof(double));
        gemm_kernel<<<P / 128, 256>>>(w3 + (long)i * 128 * 96, 128, 96, bufA, bufB, P, 1);
        finalize_kernel<<<1, 128>>>(128, P, g3 + i * 128, b3 + i * 128);

        maxpool_kernel<<<(BB * SS * 128 * 32) / 256, 256>>>(bufB, K, coffs[i], outF, P);
    }
}

// round 3
// speedup vs baseline: 1.2253x; 1.2253x over previous
#include <cuda_runtime.h>
#include <cuda_bf16.h>
#include <math.h>

#define BB 4
#define NN 8192
#define SS 2048
#define CF 64
#define OUTCH 384

// ---------------- scratch (__device__ globals; no allocation) ----------------
__device__ float g_featsT[(long)BB * NN * CF];     // [b][n][c]
__device__ float g_xyzT[(long)BB * 3 * NN];        // [b][d][n]
__device__ float g_pn2[(long)BB * NN];             // |p|^2
__device__ float g_newxyz[(long)BB * SS * 3];      // centers
__device__ float g_q2[(long)BB * SS];              // |q|^2
__device__ int   g_ballidx[(long)BB * SS * 112];   // 16+32+64 per query
__device__ float g_bufA[(long)96 * BB * SS * 64];  // 96  x 524288
__device__ float g_bufB[(long)128 * BB * SS * 64]; // 128 x 524288
__device__ double g_stats[256];                    // [sum(0..127), sumsq(128..255)]
__device__ float g_a[128];
__device__ float g_beta[128];

// ---------------- prep: transpose features, xyz SoA + |p|^2 ----------------
__global__ void transpose_feats_kernel(const float* __restrict__ f) {
    __shared__ float tile[32][33];
    int b = blockIdx.z;
    int n0 = blockIdx.x * 32, c0 = blockIdx.y * 32;
    int x = threadIdx.x, y = threadIdx.y;
    for (int r = y; r < 32; r += 8)
        tile[r][x] = f[((long)b * CF + c0 + r) * NN + n0 + x];
    __syncthreads();
    for (int r = y; r < 32; r += 8)
        g_featsT[((long)b * NN + n0 + r) * CF + c0 + x] = tile[x][r];
}

__global__ void prep_xyz_kernel(const float* __restrict__ xyz) {
    int i = blockIdx.x * blockDim.x + threadIdx.x;
    if (i >= BB * NN) return;
    int b = i / NN, n = i % NN;
    float x = xyz[(long)i * 3 + 0];
    float y = xyz[(long)i * 3 + 1];
    float z = xyz[(long)i * 3 + 2];
    g_xyzT[((long)b * 3 + 0) * NN + n] = x;
    g_xyzT[((long)b * 3 + 1) * NN + n] = y;
    g_xyzT[((long)b * 3 + 2) * NN + n] = z;
    g_pn2[i] = __fadd_rn(__fadd_rn(__fmul_rn(x, x), __fmul_rn(y, y)), __fmul_rn(z, z));
}

// ---------------- FPS: one block per batch ----------------
__global__ void fps_kernel(const float* __restrict__ xyz, float* __restrict__ out_newxyz) {
    extern __shared__ float sm[];
    float* sx = sm;
    float* sy = sm + NN;
    float* sz = sm + 2 * NN;
    __shared__ float swv[32];
    __shared__ int   swi[32];
    __shared__ int   sfar;

    int b = blockIdx.x;
    int tid = threadIdx.x;
    int lane = tid & 31, wid = tid >> 5;

    for (int i = tid; i < NN; i += 1024) {
        sx[i] = xyz[((long)b * NN + i) * 3 + 0];
        sy[i] = xyz[((long)b * NN + i) * 3 + 1];
        sz[i] = xyz[((long)b * NN + i) * 3 + 2];
    }
    float dcur[8];
#pragma unroll
    for (int j = 0; j < 8; ++j) dcur[j] = 3.4e38f;
    int far = 0;
    __syncthreads();

    for (int it = 0; it < SS; ++it) {
        float fx = sx[far], fy = sy[far], fz = sz[far];
        if (tid == 0) {
            long q = (long)b * SS + it;
            out_newxyz[q * 3 + 0] = fx;
            out_newxyz[q * 3 + 1] = fy;
            out_newxyz[q * 3 + 2] = fz;
            g_newxyz[q * 3 + 0] = fx;
            g_newxyz[q * 3 + 1] = fy;
            g_newxyz[q * 3 + 2] = fz;
            g_q2[q] = __fadd_rn(__fadd_rn(__fmul_rn(fx, fx), __fmul_rn(fy, fy)), __fmul_rn(fz, fz));
        }
        float mv = -1.0f;
        int mi = 0;
#pragma unroll
        for (int j = 0; j < 8; ++j) {
            int i = tid + j * 1024;
            float dx = __fadd_rn(sx[i], -fx);
            float dy = __fadd_rn(sy[i], -fy);
            float dz = __fadd_rn(sz[i], -fz);
            float d = __fadd_rn(__fadd_rn(__fmul_rn(dx, dx), __fmul_rn(dy, dy)), __fmul_rn(dz, dz));
            float dn = fminf(dcur[j], d);
            dcur[j] = dn;
            if (dn > mv) { mv = dn; mi = i; }
        }
#pragma unroll
        for (int off = 16; off > 0; off >>= 1) {
            float ov = __shfl_down_sync(0xffffffffu, mv, off);
            int   oi = __shfl_down_sync(0xffffffffu, mi, off);
            if (ov > mv || (ov == mv && oi < mi)) { mv = ov; mi = oi; }
        }
        if (lane == 0) { swv[wid] = mv; swi[wid] = mi; }
        __syncthreads();
        if (wid == 0) {
            float v = swv[lane];
            int   ii = swi[lane];
#pragma unroll
            for (int off = 16; off > 0; off >>= 1) {
                float ov = __shfl_down_sync(0xffffffffu, v, off);
                int   oi = __shfl_down_sync(0xffffffffu, ii, off);
                if (ov > v || (ov == v && oi < ii)) { v = ov; ii = oi; }
            }
            if (lane == 0) sfar = ii;
        }
        __syncthreads();
        far = sfar;
    }
}

// ---------------- ball query: 1 warp per (b, s), all 3 radii ----------------
__global__ void ballq_kernel() {
    int warp = (blockIdx.x * blockDim.x + threadIdx.x) >> 5;
    int lane = threadIdx.x & 31;
    if (warp >= BB * SS) return;
    int b = warp / SS;
    float qx = g_newxyz[(long)warp * 3 + 0];
    float qy = g_newxyz[(long)warp * 3 + 1];
    float qz = g_newxyz[(long)warp * 3 + 2];
    float q2 = g_q2[warp];
    const float rr0 = 0.1f * 0.1f, rr1 = 0.2f * 0.2f, rr2 = 0.4f * 0.4f;
    int c0 = 0, c1 = 0, c2 = 0;
    int f0 = NN - 1, f1 = NN - 1, f2 = NN - 1;
    int* ball = g_ballidx + (long)warp * 112;
    unsigned lanemask = (1u << lane) - 1u;

    const float* px0 = &g_xyzT[((long)b * 3 + 0) * NN];
    const float* py0 = &g_xyzT[((long)b * 3 + 1) * NN];
    const float* pz0 = &g_xyzT[((long)b * 3 + 2) * NN];
    const float* pn2a = &g_pn2[(long)b * NN];

    for (int n0 = 0; n0 < NN; n0 += 32) {
        int n = n0 + lane;
        float px = px0[n], py = py0[n], pz = pz0[n];
        float pn2 = pn2a[n];
        float dot = __fadd_rn(__fadd_rn(__fmul_rn(qx, px), __fmul_rn(qy, py)), __fmul_rn(qz, pz));
        float d2 = __fadd_rn(__fadd_rn(q2, pn2), -__fmul_rn(2.0f, dot));
        bool in0 = d2 < rr0, in1 = d2 < rr1, in2 = d2 < rr2;
        unsigned m0 = __ballot_sync(0xffffffffu, in0);
        unsigned m1 = __ballot_sync(0xffffffffu, in1);
        unsigned m2 = __ballot_sync(0xffffffffu, in2);
        if (c0 < 16) {
            if (c0 == 0 && m0) f0 = n0 + __ffs(m0) - 1;
            int pos = c0 + __popc(m0 & lanemask);
            if (in0 && pos < 16) ball[pos] = n;
            c0 = min(16, c0 + __popc(m0));
        }
        if (c1 < 32) {
            if (c1 == 0 && m1) f1 = n0 + __ffs(m1) - 1;
            int pos = c1 + __popc(m1 & lanemask);
            if (in1 && pos < 32) ball[16 + pos] = n;
            c1 = min(32, c1 + __popc(m1));
        }
        if (c2 < 64) {
            if (c2 == 0 && m2) f2 = n0 + __ffs(m2) - 1;
            int pos = c2 + __popc(m2 & lanemask);
            if (in2 && pos < 64) ball[48 + pos] = n;
            c2 = min(64, c2 + __popc(m2));
        }
        if (c0 >= 16 && c1 >= 32 && c2 >= 64) break;
    }
    for (int p = c0 + lane; p < 16; p += 32) ball[p] = f0;
    for (int p = c1 + lane; p < 32; p += 32) ball[16 + p] = f1;
    for (int p = c2 + lane; p < 64; p += 32) ball[48 + p] = f2;
}

// ---------------- gather: build x0 [67][P] ----------------
__global__ void gather_kernel(int K, int off, float* __restrict__ X, int P) {
    int p = blockIdx.x * 256 + threadIdx.x;
    if (p >= P) return;
    int q = p / K, k = p - q * K;
    int b = q / SS;
    int idx = g_ballidx[(long)q * 112 + off + k];
#pragma unroll
    for (int c = 0; c < 3; ++c)
        X[(long)c * P + p] = g_xyzT[((long)b * 3 + c) * NN + idx] - g_newxyz[(long)q * 3 + c];
    const float* fr = &g_featsT[((long)b * NN + idx) * CF];
#pragma unroll 8
    for (int c = 0; c < CF; ++c)
        X[(long)(3 + c) * P + p] = fr[c];
}

// ---------------- single-pass GEMM: W and X panels fully SMEM-resident ----------------
// O, C compile-time. Block tile O x PT. Thread tile TO x TP (TP=8).
// One global->smem load, ONE sync, then C-deep unrolled FMA loop.
template <int O, int C, int PT, int TO, bool FOLD>
__global__ void __launch_bounds__(256) gemm_t(
    const float* __restrict__ Wg, const float* __restrict__ X,
    float* __restrict__ Y, long P) {
    constexpr int TP = 8;
    constexpr int PG = PT / TP;   // threads along P (16 or 32)
    constexpr int OG = O / TO;    // threads along O
    static_assert(PG * OG == 256, "bad tiling");

    extern __shared__ float smx[];
    float* Xs = smx;              // [C][PT]
    float* Ws = smx + C * PT;     // [C][O]

    int tid = threadIdx.x;
    long p0 = (long)blockIdx.x * PT;

    // cooperative load X panel (coalesced float4), with optional BN+ReLU fold
#pragma unroll 4
    for (int i = tid; i < C * (PT / 4); i += 256) {
        int c = i / (PT / 4);
        int col = i - c * (PT / 4);
        float4 v = *(const float4*)&X[(long)c * P + p0 + col * 4];
        if (FOLD) {
            float a = g_a[c], be = g_beta[c];
            v.x = fmaxf(0.0f, fmaf(a, v.x, be));
            v.y = fmaxf(0.0f, fmaf(a, v.y, be));
            v.z = fmaxf(0.0f, fmaf(a, v.z, be));
            v.w = fmaxf(0.0f, fmaf(a, v.w, be));
        }
        *(float4*)&Xs[c * PT + col * 4] = v;
    }
    // load W transposed into smem: Ws[c][o]
    for (int i = tid; i < C * O; i += 256) {
        int o = i % O;
        int c = i / O;
        Ws[c * O + o] = Wg[(long)o * C + c];
    }
    __syncthreads();

    int pg = tid % PG;
    int og = tid / PG;

    float acc[TO][TP];
#pragma unroll
    for (int i = 0; i < TO; ++i)
#pragma unroll
        for (int j = 0; j < TP; ++j) acc[i][j] = 0.0f;

    const float* xp = Xs + pg * TP;
    const float* wp = Ws + og * TO;
#pragma unroll 4
    for (int cc = 0; cc < C; ++cc) {
        float xv[TP];
        float4 x0 = *(const float4*)&xp[cc * PT];
        float4 x1 = *(const float4*)&xp[cc * PT + 4];
        xv[0] = x0.x; xv[1] = x0.y; xv[2] = x0.z; xv[3] = x0.w;
        xv[4] = x1.x; xv[5] = x1.y; xv[6] = x1.z; xv[7] = x1.w;
        float wv[TO];
#pragma unroll
        for (int i = 0; i < TO; ++i) wv[i] = wp[cc * O + i];
#pragma unroll
        for (int i = 0; i < TO; ++i)
#pragma unroll
            for (int j = 0; j < TP; ++j)
                acc[i][j] = fmaf(wv[i], xv[j], acc[i][j]);
    }

    // epilogue: store + per-channel stats
#pragma unroll
    for (int i = 0; i < TO; ++i) {
        int o = og * TO + i;
        float s = 0.0f, sq = 0.0f;
#pragma unroll
        for (int j = 0; j < TP; ++j) {
            float v = acc[i][j];
            s += v;
            sq = fmaf(v, v, sq);
        }
        float4 v0 = make_float4(acc[i][0], acc[i][1], acc[i][2], acc[i][3]);
        float4 v1 = make_float4(acc[i][4], acc[i][5], acc[i][6], acc[i][7]);
        *(float4*)&Y[(long)o * P + p0 + pg * TP] = v0;
        *(float4*)&Y[(long)o * P + p0 + pg * TP + 4] = v1;
        // reduce across the PG threads sharing this o (contiguous segment)
#pragma unroll
        for (int off = PG / 2; off > 0; off >>= 1) {
            s  += __shfl_down_sync(0xffffffffu, s, off, PG);
            sq += __shfl_down_sync(0xffffffffu, sq, off, PG);
        }
        if (pg == 0) {
            atomicAdd(&g_stats[o], (double)s);
            atomicAdd(&g_stats[128 + o], (double)sq);
        }
    }
}

// ---------------- finalize BN params ----------------
__global__ void finalize_kernel(int O, int P, const float* __restrict__ g, const float* __restrict__ b) {
    int o = threadIdx.x;
    if (o >= O) return;
    double m = g_stats[o] / (double)P;
    double var = g_stats[128 + o] / (double)P - m * m;
    float aa = g[o] / sqrtf((float)var + 1e-5f);
    g_a[o] = aa;
    g_beta[o] = fmaf(-(float)m, aa, b[o]);
}

// ---------------- maxpool over K with BN+ReLU fold ----------------
__global__ void maxpool_kernel(const float* __restrict__ Y, int K, int coff,
                               float* __restrict__ out, int P) {
    int gw = (blockIdx.x * blockDim.x + threadIdx.x) >> 5;
    int lane = threadIdx.x & 31;
    if (gw >= BB * SS * 128) return;
    int q = gw % (BB * SS);
    int o = gw / (BB * SS);
    int b = q / SS, s = q % SS;
    float a = g_a[o], be = g_beta[o];
    const float* yp = &Y[(long)o * P + (long)q * K];
    float m = 0.0f;
    for (int k = lane; k < K; k += 32)
        m = fmaxf(m, fmaxf(0.0f, fmaf(a, yp[k], be)));
#pragma unroll
    for (int off = 16; off > 0; off >>= 1)
        m = fmaxf(m, __shfl_down_sync(0xffffffffu, m, off));
    if (lane == 0)
        out[((long)b * OUTCH + coff + o) * SS + s] = m;
}

// ---------------- launch ----------------
extern "C" void kernel_launch(void* const* d_in, const int* in_sizes, int n_in,
                              void* d_out, int out_size) {
    (void)in_sizes; (void)n_in; (void)out_size;
    const float* xyz   = (const float*)d_in[0];
    const float* feats = (const float*)d_in[1];
    const float* w1 = (const float*)d_in[2];
    const float* g1 = (const float*)d_in[3];
    const float* b1 = (const float*)d_in[4];
    const float* w2 = (const float*)d_in[5];
    const float* g2 = (const float*)d_in[6];
    const float* b2 = (const float*)d_in[7];
    const float* w3 = (const float*)d_in[8];
    const float* g3 = (const float*)d_in[9];
    const float* b3 = (const float*)d_in[10];
    float* out = (float*)d_out;
    float* outF = out + (long)BB * SS * 3;

    float *bufA = nullptr, *bufB = nullptr;
    double* stats = nullptr;
    cudaGetSymbolAddress((void**)&bufA, g_bufA);
    cudaGetSymbolAddress((void**)&bufB, g_bufB);
    cudaGetSymbolAddress((void**)&stats, g_stats);

    cudaFuncSetAttribute(fps_kernel, cudaFuncAttributeMaxDynamicSharedMemorySize, 3 * NN * 4);

    // GEMM instantiations: <O, C, PT, TO, FOLD>
    auto g1k = gemm_t<64, 67, 256, 8, false>;   // smem 67*256*4 + 67*64*4  = 85760
    auto g2k = gemm_t<96, 64, 128, 6, true>;    // smem 64*128*4 + 64*96*4  = 57344
    auto g3k = gemm_t<128, 96, 128, 8, true>;   // smem 96*128*4 + 96*128*4 = 98304
    const int smem1 = 67 * 256 * 4 + 67 * 64 * 4;
    const int smem2 = 64 * 128 * 4 + 64 * 96 * 4;
    const int smem3 = 96 * 128 * 4 + 96 * 128 * 4;
    cudaFuncSetAttribute(g1k, cudaFuncAttributeMaxDynamicSharedMemorySize, smem1);
    cudaFuncSetAttribute(g2k, cudaFuncAttributeMaxDynamicSharedMemorySize, smem2);
    cudaFuncSetAttribute(g3k, cudaFuncAttributeMaxDynamicSharedMemorySize, smem3);

    dim3 tb(32, 8), tg(NN / 32, CF / 32, BB);
    transpose_feats_kernel<<<tg, tb>>>(feats);
    prep_xyz_kernel<<<(BB * NN) / 256, 256>>>(xyz);
    fps_kernel<<<BB, 1024, 3 * NN * 4>>>(xyz, out);
    ballq_kernel<<<(BB * SS * 32) / 256, 256>>>();

    const int Ks[3] = {16, 32, 64};
    const int offs[3] = {0, 16, 48};
    const int coffs[3] = {0, 128, 256};
    for (int i = 0; i < 3; ++i) {
        int K = Ks[i];
        int P = BB * SS * K;
        gather_kernel<<<P / 256, 256>>>(K, offs[i], bufA, P);

        cudaMemsetAsync(stats, 0, 256 * sizeof(double));
        g1k<<<P / 256, 256, smem1>>>(w1 + (long)i * 64 * 67, bufA, bufB, P);
        finalize_kernel<<<1, 128>>>(64, P, g1 + i * 64, b1 + i * 64);

        cudaMemsetAsync(stats, 0, 256 * sizeof(double));
        g2k<<<P / 128, 256, smem2>>>(w2 + (long)i * 96 * 64, bufB, bufA, P);
        finalize_kernel<<<1, 128>>>(96, P, g2 + i * 96, b2 + i * 96);

        cudaMemsetAsync(stats, 0, 256 * sizeof(double));
        g3k<<<P / 128, 256, smem3>>>(w3 + (long)i * 128 * 96, bufA, bufB, P);
        finalize_kernel<<<1, 128>>>(128, P, g3 + i * 128, b3 + i * 128);

        maxpool_kernel<<<(BB * SS * 128 * 32) / 256, 256>>>(bufB, K, coffs[i], outF, P);
    }
}